// round 7
// baseline (speedup 1.0000x reference)
#include <cuda_runtime.h>
#include <cub/cub.cuh>
#include <cstdint>

#define NIMG 8
#define ATOT 65472
#define NA (NIMG*ATOT)
#define KC 6960
#define NKC (NIMG*KC)
#define NSEG 40
#define SEGCAP 2048
#define POST 2000

// ---------------- static device scratch (no runtime allocation) ----------------
__device__ unsigned long long g_k1a[NA], g_k1b[NA];
__device__ unsigned           g_v1a[NA], g_v1b[NA];
__device__ unsigned long long g_k2a[NKC], g_k2b[NKC];
__device__ unsigned           g_v2a[NKC], g_v2b[NKC];
__device__ float4             g_cbox[NKC];
__device__ float              g_score[NKC];
__device__ unsigned char      g_valid[NKC];
__device__ unsigned           g_imgmax[NIMG];            // float bits (coords >= 0)
__device__ unsigned           g_seglist[NSEG*SEGCAP];    // rank -> sorted pos q
__device__ float4             g_segbox[NSEG*SEGCAP];     // offset boxes, rank order
__device__ float              g_segarea[NSEG*SEGCAP];
__device__ unsigned long long g_seginval[NSEG*32];
__device__ unsigned long long g_mask[(size_t)NSEG*SEGCAP*32];  // ~21 MB suppression bitmask
__device__ unsigned char      g_keepq[NKC];
__device__ unsigned char      g_cubtmp[64u<<20];

// ---------------- helpers ----------------
__device__ __forceinline__ int lvl_of_anchor(int a){
    return (a<49152)?0:(a<61440)?1:(a<64512)?2:(a<65280)?3:4;
}
__device__ __forceinline__ int lvl_of_p(int p){
    return (p<2000)?0:(p<4000)?1:(p<6000)?2:(p<6768)?3:4;
}
__device__ __forceinline__ int loff_of(int l){
    return (l==0)?0:(l==1)?49152:(l==2)?61440:(l==3)?64512:65280;
}
__device__ __forceinline__ int coff_of(int l){
    return (l==0)?0:(l==1)?2000:(l==2)?4000:(l==3)?6000:6768;
}
__device__ __forceinline__ int segk_of(int l){
    return (l<3)?2000:(l==3)?768:192;
}
// ascending-orderable uint for float
__device__ __forceinline__ unsigned fordera(float f){
    unsigned b = __float_as_uint(f);
    return (b & 0x80000000u) ? ~b : (b | 0x80000000u);
}

// XLA logistic: 0.5 + 0.5*tanh(0.5x), tanh = EmitFastTanh rational (Eigen coeffs).
// Variant A: fp-contracted (FMA) Horner — matches XLA backends with contraction on.
__device__ __forceinline__ float sigmoid_ref(float x){
    float t  = __fmul_rn(0.5f, x);           // exact (power of two)
    float r;
    if (fabsf(t) < 0.0004f) {
        r = t;
    } else {
        float tc = fmaxf(-9.0f, fminf(9.0f, t));
        float s  = __fmul_rn(tc, tc);
        float p  = __fmaf_rn(s, -2.76076847742355e-16f, 2.00018790482477e-13f);
        p = __fmaf_rn(p, s, -8.60467152213735e-11f);
        p = __fmaf_rn(p, s,  5.12229709037114e-08f);
        p = __fmaf_rn(p, s,  1.48572235717979e-05f);
        p = __fmaf_rn(p, s,  6.37261928875436e-04f);
        p = __fmaf_rn(p, s,  4.89352455891786e-03f);
        p = __fmul_rn(p, tc);
        float q = __fmaf_rn(s, 1.19825839466702e-06f, 1.18534705686654e-04f);
        q = __fmaf_rn(q, s, 2.26843463243900e-03f);
        q = __fmaf_rn(q, s, 4.89352518554385e-03f);
        r = __fdiv_rn(p, q);
    }
    return __fmaf_rn(0.5f, r, 0.5f);
}

// ---------------- kernels ----------------
__global__ void k_zero(){
    int t = blockIdx.x*blockDim.x + threadIdx.x;
    if (t < NIMG)    g_imgmax[t]   = 0u;
    if (t < NSEG*32) g_seginval[t] = 0ull;
}

__global__ void k_keys1(const float* __restrict__ obj){
    int idx = blockIdx.x*blockDim.x + threadIdx.x;
    if (idx >= NA) return;
    int i = idx / ATOT, a = idx % ATOT;
    int l = lvl_of_anchor(a);
    unsigned d = ~fordera(obj[idx]);          // descending objectness
    g_k1a[idx] = ((unsigned long long)(i*5+l) << 32) | d;
    g_v1a[idx] = (unsigned)a;
}

__global__ void k_cand(const float* __restrict__ props, const float* __restrict__ obj){
    int idx = blockIdx.x*blockDim.x + threadIdx.x;
    if (idx >= NKC) return;
    int i = idx / KC, p = idx % KC;
    int l = lvl_of_p(p);
    int r = p - coff_of(l);
    int srt = i*ATOT + loff_of(l) + r;        // r-th best of segment in sort1 output
    int a   = (int)g_v1b[srt];
    int gi  = i*ATOT + a;
    float o = obj[gi];
    float4 b = *(const float4*)(props + (size_t)gi*4);
    float x1 = fminf(fmaxf(b.x, 0.f), 512.f);
    float y1 = fminf(fmaxf(b.y, 0.f), 512.f);
    float x2 = fminf(fmaxf(b.z, 0.f), 512.f);
    float y2 = fminf(fmaxf(b.w, 0.f), 512.f);
    float sc = sigmoid_ref(o);
    float ws = __fsub_rn(x2, x1), hs = __fsub_rn(y2, y1);
    unsigned char v = (ws >= 0.001f) && (hs >= 0.001f) && (sc >= 0.0f);
    g_cbox[idx]  = make_float4(x1, y1, x2, y2);
    g_score[idx] = sc;
    g_valid[idx] = v;
    float mx = fmaxf(fmaxf(x1, y1), fmaxf(x2, y2));
    atomicMax(&g_imgmax[i], __float_as_uint(mx));
}

__global__ void k_keys2(){
    int idx = blockIdx.x*blockDim.x + threadIdx.x;
    if (idx >= NKC) return;
    int i = idx / KC, p = idx % KC;
    float f = g_valid[idx] ? g_score[idx] : -INFINITY;
    unsigned d = ~fordera(f);                 // descending score; -inf last
    g_k2a[idx] = ((unsigned long long)i << 45) |
                 ((unsigned long long)d << 13) | (unsigned long long)p;
    g_v2a[idx] = (unsigned)p;
}

__global__ void __launch_bounds__(512) k_rank(){
    int i = blockIdx.x, t = threadIdx.x;
    typedef cub::BlockScan<unsigned long long, 512> BS;
    __shared__ typename BS::TempStorage ts;
    unsigned long long items[14], ex[14];
    signed char lv[14];
#pragma unroll
    for (int j = 0; j < 14; j++){
        int q = t*14 + j;
        if (q < KC){
            int p = (int)g_v2b[i*KC + q];
            int l = lvl_of_p(p);
            lv[j] = (signed char)l;
            items[j] = 1ull << (12*l);
        } else { lv[j] = -1; items[j] = 0ull; }
    }
    BS(ts).ExclusiveSum(items, ex);
#pragma unroll
    for (int j = 0; j < 14; j++){
        if (lv[j] >= 0){
            int l = (int)lv[j];
            int rank = (int)((ex[j] >> (12*l)) & 0xFFFull);
            g_seglist[(i*5 + l)*SEGCAP + rank] = (unsigned)(t*14 + j);
        }
    }
}

__global__ void k_pack(){
    int u = blockIdx.x*blockDim.x + threadIdx.x;   // seg*SEGCAP + rank
    if (u >= NSEG*SEGCAP) return;
    int seg = u >> 11, r = u & 2047;
    int l = seg % 5, i = seg / 5;
    int m = segk_of(l);
    if (r < m){
        int q = (int)g_seglist[u];
        int p = (int)g_v2b[i*KC + q];
        int cand = i*KC + p;
        float4 b = g_cbox[cand];
        float mp1 = __fadd_rn(__uint_as_float(g_imgmax[i]), 1.0f);
        float off = __fmul_rn((float)l, mp1);
        float4 ob = make_float4(__fadd_rn(b.x, off), __fadd_rn(b.y, off),
                                __fadd_rn(b.z, off), __fadd_rn(b.w, off));
        g_segbox[u]  = ob;
        g_segarea[u] = __fmul_rn(__fsub_rn(ob.z, ob.x), __fsub_rn(ob.w, ob.y));
        if (!g_valid[cand])
            atomicOr(&g_seginval[seg*32 + (r >> 6)], 1ull << (r & 63));
    } else {
        atomicOr(&g_seginval[seg*32 + (r >> 6)], 1ull << (r & 63));
    }
}

__global__ void k_iou(){
    int seg = blockIdx.y;
    int u = blockIdx.x*blockDim.x + threadIdx.x;   // row*32 + word
    int row = u >> 5, w = u & 31;
    int m = segk_of(seg % 5);
    if (row >= m) return;
    size_t base = (size_t)seg * SEGCAP;
    unsigned long long bits = 0ull;
    int j0 = w * 64;
    if (j0 < m && j0 + 63 > row){
        float4 A = g_segbox[base + row];
        float aA = g_segarea[base + row];
        int jend = min(j0 + 64, m);
        for (int j = max(j0, row + 1); j < jend; j++){
            float4 B = g_segbox[base + j];
            float aB = g_segarea[base + j];
            float ltx = fmaxf(A.x, B.x), lty = fmaxf(A.y, B.y);
            float rbx = fminf(A.z, B.z), rby = fminf(A.w, B.w);
            float ww = fmaxf(__fsub_rn(rbx, ltx), 0.f);
            float hh = fmaxf(__fsub_rn(rby, lty), 0.f);
            float inter = __fmul_rn(ww, hh);
            float iou = __fdiv_rn(inter, __fsub_rn(__fadd_rn(aA, aB), inter));
            if (iou > 0.7f) bits |= 1ull << (j - j0);
        }
    }
    g_mask[(base + row)*32 + w] = bits;
}

__global__ void k_sweep(){
    int seg = blockIdx.x, lane = threadIdx.x;
    int l = seg % 5, i = seg / 5, m = segk_of(l);
    size_t mb = (size_t)seg * SEGCAP * 32;
    unsigned long long removed = g_seginval[seg*32 + lane];
    unsigned long long buf[8];
#pragma unroll
    for (int k = 0; k < 8; k++)
        buf[k] = (k < m) ? g_mask[mb + (size_t)k*32 + lane] : 0ull;
    for (int basei = 0; basei < m; basei += 8){
        unsigned long long nbuf[8];
#pragma unroll
        for (int k = 0; k < 8; k++){
            int rr = basei + 8 + k;
            nbuf[k] = (rr < m) ? g_mask[mb + (size_t)rr*32 + lane] : 0ull;
        }
#pragma unroll
        for (int k = 0; k < 8; k++){
            int ii = basei + k;
            if (ii >= m) break;                       // uniform
            unsigned long long rw = __shfl_sync(0xFFFFFFFFu, removed, ii >> 6);
            if (!((rw >> (ii & 63)) & 1ull)) removed |= buf[k];
        }
#pragma unroll
        for (int k = 0; k < 8; k++) buf[k] = nbuf[k];
    }
    for (int b = 0; b < 64; b++){
        int r = lane*64 + b;
        if (r < m){
            unsigned q = g_seglist[seg*SEGCAP + r];
            g_keepq[i*KC + q] = (unsigned char)(((removed >> b) & 1ull) ^ 1ull);
        }
    }
}

__global__ void __launch_bounds__(512) k_out(float* __restrict__ out){
    int i = blockIdx.x, t = threadIdx.x;
    typedef cub::BlockScan<int, 512> BS;
    __shared__ typename BS::TempStorage ts;
    __shared__ int s_tot;
    int kp[14], ex[14];
#pragma unroll
    for (int j = 0; j < 14; j++){
        int q = t*14 + j;
        kp[j] = (q < KC) ? (int)g_keepq[i*KC + q] : 0;
    }
    int agg;
    BS(ts).ExclusiveSum(kp, ex, agg);
    if (t == 0) s_tot = agg;
    __syncthreads();
    float* ob = out + (size_t)i*POST*4;
    float* os = out + (size_t)NIMG*POST*4 + (size_t)i*POST;
#pragma unroll
    for (int j = 0; j < 14; j++){
        int q = t*14 + j;
        if (q < KC && kp[j] && ex[j] < POST){
            int p = (int)g_v2b[i*KC + q];
            int cand = i*KC + p;
            *(float4*)(ob + ex[j]*4) = g_cbox[cand];
            os[ex[j]] = g_score[cand];
        }
    }
    int T = min(s_tot, POST);
    for (int s = T + t; s < POST; s += 512){
        *(float4*)(ob + s*4) = make_float4(0.f, 0.f, 0.f, 0.f);
        os[s] = 0.f;
    }
}

// ---------------- launch ----------------
extern "C" void kernel_launch(void* const* d_in, const int* in_sizes, int n_in,
                              void* d_out, int out_size){
    const float* props = (const float*)d_in[0];
    const float* obj   = (const float*)d_in[1];
    float* out = (float*)d_out;

    void *pk1a, *pk1b, *pv1a, *pv1b, *pk2a, *pk2b, *pv2a, *pv2b, *ptmp;
    cudaGetSymbolAddress(&pk1a, g_k1a); cudaGetSymbolAddress(&pk1b, g_k1b);
    cudaGetSymbolAddress(&pv1a, g_v1a); cudaGetSymbolAddress(&pv1b, g_v1b);
    cudaGetSymbolAddress(&pk2a, g_k2a); cudaGetSymbolAddress(&pk2b, g_k2b);
    cudaGetSymbolAddress(&pv2a, g_v2a); cudaGetSymbolAddress(&pv2b, g_v2b);
    cudaGetSymbolAddress(&ptmp, g_cubtmp);

    k_zero<<<5, 256>>>();
    k_keys1<<<(NA + 255)/256, 256>>>(obj);

    size_t tb = sizeof(g_cubtmp);
    cub::DeviceRadixSort::SortPairs(ptmp, tb,
        (const unsigned long long*)pk1a, (unsigned long long*)pk1b,
        (const unsigned*)pv1a, (unsigned*)pv1b, NA, 0, 38);

    k_cand<<<(NKC + 255)/256, 256>>>(props, obj);
    k_keys2<<<(NKC + 255)/256, 256>>>();

    size_t tb2 = sizeof(g_cubtmp);
    cub::DeviceRadixSort::SortPairs(ptmp, tb2,
        (const unsigned long long*)pk2a, (unsigned long long*)pk2b,
        (const unsigned*)pv2a, (unsigned*)pv2b, NKC, 0, 48);

    k_rank<<<NIMG, 512>>>();
    k_pack<<<(NSEG*SEGCAP + 255)/256, 256>>>();
    dim3 giou(SEGCAP*32/256, NSEG);
    k_iou<<<giou, 256>>>();
    k_sweep<<<NSEG, 32>>>();
    k_out<<<NIMG, 512>>>(out);
}

// round 8
// speedup vs baseline: 1.7202x; 1.7202x over previous
#include <cuda_runtime.h>
#include <cub/cub.cuh>
#include <cstdint>

#define NIMG 8
#define ATOT 65472
#define NA (NIMG*ATOT)
#define KC 6960
#define NKC (NIMG*KC)
#define NSEG 40
#define SEGCAP 2048
#define POST 2000
#define AMB_CAP 65536

// ---------------- static device scratch (no runtime allocation) ----------------
__device__ unsigned long long g_k1a[NA], g_k1b[NA];
__device__ unsigned           g_v1a[NA], g_v1b[NA];
__device__ unsigned long long g_k2a[NKC], g_k2b[NKC];
__device__ unsigned           g_v2a[NKC], g_v2b[NKC];
__device__ float4             g_cbox[NKC];
__device__ float              g_score[NKC];
__device__ unsigned char      g_valid[NKC];
__device__ unsigned           g_imgmax[NIMG];            // float bits (coords >= 0)
__device__ unsigned           g_seglist[NSEG*SEGCAP];    // rank -> sorted pos q
__device__ float4             g_segbox[NSEG*SEGCAP];     // offset boxes, rank order
__device__ float              g_segarea[NSEG*SEGCAP];
__device__ unsigned long long g_seginval[NSEG*32];
__device__ unsigned long long g_mask[(size_t)NSEG*SEGCAP*32];  // ~21 MB suppression bitmask
__device__ unsigned char      g_keepq[NKC];
__device__ unsigned           g_ambcnt;
__device__ unsigned           g_amb[AMB_CAP];
__device__ unsigned char      g_cubtmp[64u<<20];

// ---------------- helpers ----------------
__device__ __forceinline__ int lvl_of_anchor(int a){
    return (a<49152)?0:(a<61440)?1:(a<64512)?2:(a<65280)?3:4;
}
__device__ __forceinline__ int lvl_of_p(int p){
    return (p<2000)?0:(p<4000)?1:(p<6000)?2:(p<6768)?3:4;
}
__device__ __forceinline__ int loff_of(int l){
    return (l==0)?0:(l==1)?49152:(l==2)?61440:(l==3)?64512:65280;
}
__device__ __forceinline__ int coff_of(int l){
    return (l==0)?0:(l==1)?2000:(l==2)?4000:(l==3)?6000:6768;
}
__device__ __forceinline__ int segk_of(int l){
    return (l<3)?2000:(l==3)?768:192;
}
// ascending-orderable uint for float
__device__ __forceinline__ unsigned fordera(float f){
    unsigned b = __float_as_uint(f);
    return (b & 0x80000000u) ? ~b : (b | 0x80000000u);
}

// XLA logistic: 0.5 + 0.5*tanh(0.5x), tanh = EmitFastTanh rational (Eigen coeffs).
__device__ __forceinline__ float sigmoid_ref(float x){
    float t  = __fmul_rn(0.5f, x);
    float r;
    if (fabsf(t) < 0.0004f) {
        r = t;
    } else {
        float tc = fmaxf(-9.0f, fminf(9.0f, t));
        float s  = __fmul_rn(tc, tc);
        float p  = __fmaf_rn(s, -2.76076847742355e-16f, 2.00018790482477e-13f);
        p = __fmaf_rn(p, s, -8.60467152213735e-11f);
        p = __fmaf_rn(p, s,  5.12229709037114e-08f);
        p = __fmaf_rn(p, s,  1.48572235717979e-05f);
        p = __fmaf_rn(p, s,  6.37261928875436e-04f);
        p = __fmaf_rn(p, s,  4.89352455891786e-03f);
        p = __fmul_rn(p, tc);
        float q = __fmaf_rn(s, 1.19825839466702e-06f, 1.18534705686654e-04f);
        q = __fmaf_rn(q, s, 2.26843463243900e-03f);
        q = __fmaf_rn(q, s, 4.89352518554385e-03f);
        r = __fdiv_rn(p, q);
    }
    return __fmaf_rn(0.5f, r, 0.5f);
}

// Exact predicate: RN(a/u) > 0.7f  <=>  a/u >= m,  m = 0.7f + 2^-25 = 23488103*2^-25.
// (0.7f mantissa odd -> exact tie rounds up to 0.7f's successor -> boundary inclusive.)
__device__ __forceinline__ bool exact_pred(float a, float u){
    if (!(a > 0.f) || !(u > 0.f)) return false;
    unsigned ia = __float_as_uint(a), iu = __float_as_uint(u);
    int d = (int)(ia >> 23) - (int)(iu >> 23);
    if (d > 0)  return true;
    if (d < -1) return false;
    unsigned long long Ma = (ia & 0x7FFFFFu) | 0x800000u;
    unsigned long long Mu = (iu & 0x7FFFFFu) | 0x800000u;
    return (Ma << (d + 25)) >= 23488103ull * Mu;
}

// ---------------- kernels ----------------
__global__ void k_zero(){
    int t = blockIdx.x*blockDim.x + threadIdx.x;
    if (t < NIMG)    g_imgmax[t]   = 0u;
    if (t < NSEG*32) g_seginval[t] = 0ull;
    if (t == 0)      g_ambcnt = 0u;
}

__global__ void k_keys1(const float* __restrict__ obj){
    int idx = blockIdx.x*blockDim.x + threadIdx.x;
    if (idx >= NA) return;
    int i = idx / ATOT, a = idx % ATOT;
    int l = lvl_of_anchor(a);
    unsigned d = ~fordera(obj[idx]);          // descending objectness
    g_k1a[idx] = ((unsigned long long)(i*5+l) << 32) | d;
    g_v1a[idx] = (unsigned)a;
}

__global__ void k_cand(const float* __restrict__ props, const float* __restrict__ obj){
    int idx = blockIdx.x*blockDim.x + threadIdx.x;
    if (idx >= NKC) return;
    int i = idx / KC, p = idx % KC;
    int l = lvl_of_p(p);
    int r = p - coff_of(l);
    int srt = i*ATOT + loff_of(l) + r;
    int a   = (int)g_v1b[srt];
    int gi  = i*ATOT + a;
    float o = obj[gi];
    float4 b = *(const float4*)(props + (size_t)gi*4);
    float x1 = fminf(fmaxf(b.x, 0.f), 512.f);
    float y1 = fminf(fmaxf(b.y, 0.f), 512.f);
    float x2 = fminf(fmaxf(b.z, 0.f), 512.f);
    float y2 = fminf(fmaxf(b.w, 0.f), 512.f);
    float sc = sigmoid_ref(o);
    float ws = __fsub_rn(x2, x1), hs = __fsub_rn(y2, y1);
    unsigned char v = (ws >= 0.001f) && (hs >= 0.001f) && (sc >= 0.0f);
    g_cbox[idx]  = make_float4(x1, y1, x2, y2);
    g_score[idx] = sc;
    g_valid[idx] = v;
    float mx = fmaxf(fmaxf(x1, y1), fmaxf(x2, y2));
    atomicMax(&g_imgmax[i], __float_as_uint(mx));
}

__global__ void k_keys2(){
    int idx = blockIdx.x*blockDim.x + threadIdx.x;
    if (idx >= NKC) return;
    int i = idx / KC, p = idx % KC;
    float f = g_valid[idx] ? g_score[idx] : -INFINITY;
    unsigned d = ~fordera(f);                 // descending score; -inf last
    g_k2a[idx] = ((unsigned long long)i << 45) |
                 ((unsigned long long)d << 13) | (unsigned long long)p;
    g_v2a[idx] = (unsigned)p;
}

__global__ void __launch_bounds__(512) k_rank(){
    int i = blockIdx.x, t = threadIdx.x;
    typedef cub::BlockScan<unsigned long long, 512> BS;
    __shared__ typename BS::TempStorage ts;
    unsigned long long items[14], ex[14];
    signed char lv[14];
#pragma unroll
    for (int j = 0; j < 14; j++){
        int q = t*14 + j;
        if (q < KC){
            int p = (int)g_v2b[i*KC + q];
            int l = lvl_of_p(p);
            lv[j] = (signed char)l;
            items[j] = 1ull << (12*l);
        } else { lv[j] = -1; items[j] = 0ull; }
    }
    BS(ts).ExclusiveSum(items, ex);
#pragma unroll
    for (int j = 0; j < 14; j++){
        if (lv[j] >= 0){
            int l = (int)lv[j];
            int rank = (int)((ex[j] >> (12*l)) & 0xFFFull);
            g_seglist[(i*5 + l)*SEGCAP + rank] = (unsigned)(t*14 + j);
        }
    }
}

__global__ void k_pack(){
    int u = blockIdx.x*blockDim.x + threadIdx.x;   // seg*SEGCAP + rank
    if (u >= NSEG*SEGCAP) return;
    int seg = u >> 11, r = u & 2047;
    int l = seg % 5, i = seg / 5;
    int m = segk_of(l);
    if (r < m){
        int q = (int)g_seglist[u];
        int p = (int)g_v2b[i*KC + q];
        int cand = i*KC + p;
        float4 b = g_cbox[cand];
        float mp1 = __fadd_rn(__uint_as_float(g_imgmax[i]), 1.0f);
        float off = __fmul_rn((float)l, mp1);
        float4 ob = make_float4(__fadd_rn(b.x, off), __fadd_rn(b.y, off),
                                __fadd_rn(b.z, off), __fadd_rn(b.w, off));
        g_segbox[u]  = ob;
        g_segarea[u] = __fmul_rn(__fsub_rn(ob.z, ob.x), __fsub_rn(ob.w, ob.y));
        if (!g_valid[cand])
            atomicOr(&g_seginval[seg*32 + (r >> 6)], 1ull << (r & 63));
    } else {
        atomicOr(&g_seginval[seg*32 + (r >> 6)], 1ull << (r & 63));
    }
}

// IoU mask: warp = (rowBlk, word); lanes = 32 consecutive rows; 4 rows/thread.
// All lanes read the SAME B record per iteration -> L1 broadcast (1 line/warp-LDG).
// Division-free threshold test with rare-ambiguity flagging (resolved in k_fix).
__global__ void __launch_bounds__(256) k_iou(){
    int seg = blockIdx.y;
    int m = segk_of(seg % 5);
    int gw = blockIdx.x*8 + (threadIdx.x >> 5);     // 0..511 per seg
    int lane = threadIdx.x & 31;
    int w = gw & 31;                                // column word
    int rowBlk = gw >> 5;                           // 0..15 (128 rows each)
    int row0 = rowBlk*128;
    if (row0 >= m) return;                          // rows never read
    size_t base = (size_t)seg * SEGCAP;
    int j0 = w * 64;

    int rows[4];
#pragma unroll
    for (int k = 0; k < 4; k++) rows[k] = row0 + k*32 + lane;

    unsigned long long bits[4] = {0,0,0,0}, amb[4] = {0,0,0,0};

    // warp-uniform skip: whole word at/below every row in the tile
    if (j0 + 63 > row0){
        float4 A[4]; float aA[4];
#pragma unroll
        for (int k = 0; k < 4; k++){
            A[k]  = g_segbox[base + rows[k]];
            aA[k] = g_segarea[base + rows[k]];
        }
        int jend = min(j0 + 64, m);
        for (int j = j0; j < jend; j++){
            float4 B = __ldg(&g_segbox[base + j]);
            float aB = __ldg(&g_segarea[base + j]);
            unsigned long long bm = 1ull << (j - j0);
#pragma unroll
            for (int k = 0; k < 4; k++){
                float ltx = fmaxf(A[k].x, B.x), lty = fmaxf(A[k].y, B.y);
                float rbx = fminf(A[k].z, B.z), rby = fminf(A[k].w, B.w);
                float ww = fmaxf(__fsub_rn(rbx, ltx), 0.f);
                float hh = fmaxf(__fsub_rn(rby, lty), 0.f);
                float inter = __fmul_rn(ww, hh);
                float s = __fadd_rn(aA[k], aB);
                float u = __fsub_rn(s, inter);
                float t = __fmaf_rn(0.7f, u, -inter);   // ~ 0.7u - inter, exactly rounded
                float tau = __fmul_rn(u, 2.384185791015625e-7f);  // u * 2^-22
                if (t < -tau)        bits[k] |= bm;      // surely suppress
                if (fabsf(t) <= tau) amb[k]  |= bm;      // ambiguous -> exact fixup
            }
        }
    }
    // clear sub-diagonal bits (j <= row) once per word, then store
#pragma unroll
    for (int k = 0; k < 4; k++){
        int cnt = rows[k] - j0 + 1;
        unsigned long long lowm = (cnt <= 0) ? 0ull :
                                  (cnt >= 64) ? ~0ull : ((1ull << cnt) - 1ull);
        bits[k] &= ~lowm;
        amb[k]  &= ~lowm;
        g_mask[(base + rows[k])*32 + w] = bits[k];
        unsigned long long am = amb[k];
        while (am){
            int b = __ffsll((long long)am) - 1;
            am &= am - 1ull;
            unsigned slot = atomicAdd(&g_ambcnt, 1u);
            if (slot < AMB_CAP)
                g_amb[slot] = ((unsigned)seg << 22) | ((unsigned)rows[k] << 11)
                            | (unsigned)(j0 + b);
        }
    }
}

// Resolve ambiguous pairs with the exact integer predicate; flip mask bit on disagreement.
__global__ void k_fix(){
    unsigned n = g_ambcnt; if (n > AMB_CAP) n = AMB_CAP;
    for (unsigned t = blockIdx.x*blockDim.x + threadIdx.x; t < n;
         t += gridDim.x*blockDim.x){
        unsigned e = g_amb[t];
        int seg = (int)(e >> 22), row = (int)((e >> 11) & 0x7FFu), j = (int)(e & 0x7FFu);
        size_t base = (size_t)seg * SEGCAP;
        float4 A = g_segbox[base + row]; float aA = g_segarea[base + row];
        float4 B = g_segbox[base + j];   float aB = g_segarea[base + j];
        float ltx = fmaxf(A.x, B.x), lty = fmaxf(A.y, B.y);
        float rbx = fminf(A.z, B.z), rby = fminf(A.w, B.w);
        float ww = fmaxf(__fsub_rn(rbx, ltx), 0.f);
        float hh = fmaxf(__fsub_rn(rby, lty), 0.f);
        float inter = __fmul_rn(ww, hh);
        float u = __fsub_rn(__fadd_rn(aA, aB), inter);
        float tt = __fmaf_rn(0.7f, u, -inter);
        float tau = __fmul_rn(u, 2.384185791015625e-7f);
        bool guess = (tt < -tau);
        bool ex = exact_pred(inter, u);
        if (ex != guess)
            atomicXor(&g_mask[(base + row)*32 + (j >> 6)], 1ull << (j & 63));
    }
}

__global__ void k_sweep(){
    int seg = blockIdx.x, lane = threadIdx.x;
    int l = seg % 5, i = seg / 5, m = segk_of(l);
    size_t mb = (size_t)seg * SEGCAP * 32;
    unsigned long long removed = g_seginval[seg*32 + lane];
    unsigned long long buf[8];
#pragma unroll
    for (int k = 0; k < 8; k++)
        buf[k] = (k < m) ? g_mask[mb + (size_t)k*32 + lane] : 0ull;
    for (int basei = 0; basei < m; basei += 8){
        unsigned long long nbuf[8];
#pragma unroll
        for (int k = 0; k < 8; k++){
            int rr = basei + 8 + k;
            nbuf[k] = (rr < m) ? g_mask[mb + (size_t)rr*32 + lane] : 0ull;
        }
#pragma unroll
        for (int k = 0; k < 8; k++){
            int ii = basei + k;
            if (ii >= m) break;                       // uniform
            unsigned long long rw = __shfl_sync(0xFFFFFFFFu, removed, ii >> 6);
            if (!((rw >> (ii & 63)) & 1ull)) removed |= buf[k];
        }
#pragma unroll
        for (int k = 0; k < 8; k++) buf[k] = nbuf[k];
    }
    for (int b = 0; b < 64; b++){
        int r = lane*64 + b;
        if (r < m){
            unsigned q = g_seglist[seg*SEGCAP + r];
            g_keepq[i*KC + q] = (unsigned char)(((removed >> b) & 1ull) ^ 1ull);
        }
    }
}

__global__ void __launch_bounds__(512) k_out(float* __restrict__ out){
    int i = blockIdx.x, t = threadIdx.x;
    typedef cub::BlockScan<int, 512> BS;
    __shared__ typename BS::TempStorage ts;
    __shared__ int s_tot;
    int kp[14], ex[14];
#pragma unroll
    for (int j = 0; j < 14; j++){
        int q = t*14 + j;
        kp[j] = (q < KC) ? (int)g_keepq[i*KC + q] : 0;
    }
    int agg;
    BS(ts).ExclusiveSum(kp, ex, agg);
    if (t == 0) s_tot = agg;
    __syncthreads();
    float* ob = out + (size_t)i*POST*4;
    float* os = out + (size_t)NIMG*POST*4 + (size_t)i*POST;
#pragma unroll
    for (int j = 0; j < 14; j++){
        int q = t*14 + j;
        if (q < KC && kp[j] && ex[j] < POST){
            int p = (int)g_v2b[i*KC + q];
            int cand = i*KC + p;
            *(float4*)(ob + ex[j]*4) = g_cbox[cand];
            os[ex[j]] = g_score[cand];
        }
    }
    int T = min(s_tot, POST);
    for (int s = T + t; s < POST; s += 512){
        *(float4*)(ob + s*4) = make_float4(0.f, 0.f, 0.f, 0.f);
        os[s] = 0.f;
    }
}

// ---------------- launch ----------------
extern "C" void kernel_launch(void* const* d_in, const int* in_sizes, int n_in,
                              void* d_out, int out_size){
    const float* props = (const float*)d_in[0];
    const float* obj   = (const float*)d_in[1];
    float* out = (float*)d_out;

    void *pk1a, *pk1b, *pv1a, *pv1b, *pk2a, *pk2b, *pv2a, *pv2b, *ptmp;
    cudaGetSymbolAddress(&pk1a, g_k1a); cudaGetSymbolAddress(&pk1b, g_k1b);
    cudaGetSymbolAddress(&pv1a, g_v1a); cudaGetSymbolAddress(&pv1b, g_v1b);
    cudaGetSymbolAddress(&pk2a, g_k2a); cudaGetSymbolAddress(&pk2b, g_k2b);
    cudaGetSymbolAddress(&pv2a, g_v2a); cudaGetSymbolAddress(&pv2b, g_v2b);
    cudaGetSymbolAddress(&ptmp, g_cubtmp);

    k_zero<<<5, 256>>>();
    k_keys1<<<(NA + 255)/256, 256>>>(obj);

    size_t tb = sizeof(g_cubtmp);
    cub::DeviceRadixSort::SortPairs(ptmp, tb,
        (const unsigned long long*)pk1a, (unsigned long long*)pk1b,
        (const unsigned*)pv1a, (unsigned*)pv1b, NA, 0, 38);

    k_cand<<<(NKC + 255)/256, 256>>>(props, obj);
    k_keys2<<<(NKC + 255)/256, 256>>>();

    size_t tb2 = sizeof(g_cubtmp);
    cub::DeviceRadixSort::SortPairs(ptmp, tb2,
        (const unsigned long long*)pk2a, (unsigned long long*)pk2b,
        (const unsigned*)pv2a, (unsigned*)pv2b, NKC, 0, 48);

    k_rank<<<NIMG, 512>>>();
    k_pack<<<(NSEG*SEGCAP + 255)/256, 256>>>();
    dim3 giou(64, NSEG);
    k_iou<<<giou, 256>>>();
    k_fix<<<4, 256>>>();
    k_sweep<<<NSEG, 32>>>();
    k_out<<<NIMG, 512>>>(out);
}